// round 7
// baseline (speedup 1.0000x reference)
#include <cuda_runtime.h>
#include <cuda_bf16.h>
#include <stdint.h>
#include <math.h>

#define Bn   4
#define Tn   2048
#define En   1024
#define Hn   16
#define HDn  64
#define Mn   (Bn * Tn)          // 8192
#define QKVN (3 * En)           // 3072
#define GK   3072               // split K' = 3*E for bf16x3 trick

// ---------------- scratch (__device__ globals; no cudaMalloc allowed) -------
__device__ float g_qkv[(size_t)Mn * QKVN];            // 96 MB fp32
__device__ float g_ctx[(size_t)Mn * En];              // 32 MB fp32
__device__ __nv_bfloat16 g_xs [(size_t)Mn * GK];      // 48 MB  x split
__device__ __nv_bfloat16 g_ws [(size_t)QKVN * GK];    // 18 MB  qkv_w split
__device__ __nv_bfloat16 g_cs [(size_t)Mn * GK];      // 48 MB  ctx split
__device__ __nv_bfloat16 g_pws[(size_t)En * GK];      //  6 MB  proj_w split

// ---------------- helpers (sm_80/90 feature set only) -----------------------
__device__ __forceinline__ uint32_t smem_u32(const void* p) {
    uint32_t a;
    asm("{ .reg .u64 t; cvta.to.shared.u64 t, %1; cvt.u32.u64 %0, t; }"
        : "=r"(a) : "l"(p));
    return a;
}
__device__ __forceinline__ void cp16(uint32_t saddr, const void* g) {
    asm volatile("cp.async.cg.shared.global [%0], [%1], 16;"
                 :: "r"(saddr), "l"(g));
}
template <int N>
__device__ __forceinline__ void cp_wait() {
    asm volatile("cp.async.wait_group %0;" :: "n"(N) : "memory");
}
__device__ __forceinline__ void cp_commit() {
    asm volatile("cp.async.commit_group;" ::: "memory");
}
__device__ __forceinline__ void ldsm4(uint32_t& r0, uint32_t& r1,
                                      uint32_t& r2, uint32_t& r3,
                                      uint32_t addr) {
    asm volatile("ldmatrix.sync.aligned.m8n8.x4.shared.b16 {%0,%1,%2,%3}, [%4];"
                 : "=r"(r0), "=r"(r1), "=r"(r2), "=r"(r3) : "r"(addr));
}
__device__ __forceinline__ void mma16816(float* d, const uint32_t* a,
                                         uint32_t b0, uint32_t b1) {
    asm volatile(
        "mma.sync.aligned.m16n8k16.row.col.f32.bf16.bf16.f32 "
        "{%0,%1,%2,%3}, {%4,%5,%6,%7}, {%8,%9}, {%0,%1,%2,%3};"
        : "+f"(d[0]), "+f"(d[1]), "+f"(d[2]), "+f"(d[3])
        : "r"(a[0]), "r"(a[1]), "r"(a[2]), "r"(a[3]), "r"(b0), "r"(b1));
}
__device__ __forceinline__ uint32_t sw128(uint32_t off) {
    return off ^ ((off >> 3) & 0x70);
}
// tf32 helpers
__device__ __forceinline__ uint32_t f2tf(float x) {
    uint32_t r;
    asm("cvt.rna.tf32.f32 %0, %1;" : "=r"(r) : "f"(x));
    return r;
}
__device__ __forceinline__ void mma_tf32(float* d, uint32_t a0, uint32_t a1,
                                         uint32_t a2, uint32_t a3,
                                         uint32_t b0, uint32_t b1) {
    asm volatile(
        "mma.sync.aligned.m16n8k8.row.col.f32.tf32.tf32.f32 "
        "{%0,%1,%2,%3}, {%4,%5,%6,%7}, {%8,%9}, {%0,%1,%2,%3};"
        : "+f"(d[0]), "+f"(d[1]), "+f"(d[2]), "+f"(d[3])
        : "r"(a0), "r"(a1), "r"(a2), "r"(a3), "r"(b0), "r"(b1));
}

// ---------------------------------------------------------------------------
// bf16x3 split conversion
// ---------------------------------------------------------------------------
struct bf16x4 { __nv_bfloat162 a, b; };

__global__ void split3_kernel(const float* __restrict__ in,
                              __nv_bfloat16* __restrict__ out, int lo_sec) {
    size_t i = ((size_t)blockIdx.x * blockDim.x + threadIdx.x) * 4;
    size_t row = i >> 10;          // K = 1024
    int col = (int)(i & 1023);
    float4 v = *(const float4*)(in + i);
    float xs[4] = {v.x, v.y, v.z, v.w};
    __nv_bfloat16 h[4], l[4];
#pragma unroll
    for (int j = 0; j < 4; j++) {
        h[j] = __float2bfloat16_rn(xs[j]);
        l[j] = __float2bfloat16_rn(xs[j] - __bfloat162float(h[j]));
    }
    bf16x4 hv, lv;
    hv.a = __nv_bfloat162(h[0], h[1]); hv.b = __nv_bfloat162(h[2], h[3]);
    lv.a = __nv_bfloat162(l[0], l[1]); lv.b = __nv_bfloat162(l[2], l[3]);
    __nv_bfloat16* o = out + row * GK;
    *(bf16x4*)(o + col) = hv;
    *(bf16x4*)(o + (3 - lo_sec) * 1024 + col) = hv;
    *(bf16x4*)(o + lo_sec * 1024 + col) = lv;
}

// ---------------------------------------------------------------------------
// HMMA bf16 GEMM (verified round 4)
// ---------------------------------------------------------------------------
#define GEMM_SMEM 65536

__global__ __launch_bounds__(256, 2)
void gemm_hmma(const __nv_bfloat16* __restrict__ A,
               const __nv_bfloat16* __restrict__ B,
               const float* __restrict__ bias,
               float* __restrict__ C, int Np) {
    extern __shared__ char gsm[];
    uint32_t sb = smem_u32(gsm);
    const uint32_t SA = 0, SBB = 32768;

    int tid = threadIdx.x;
    int lane = tid & 31;
    int wid = tid >> 5;
    int wm = wid & 3;
    int wn = wid >> 2;
    int m0 = blockIdx.y * 128;
    int n0 = blockIdx.x * 128;

    uint32_t a_soff[4]; const char* a_g[4];
    uint32_t b_soff[4]; const char* b_g[4];
#pragma unroll
    for (int i = 0; i < 4; i++) {
        int c = tid + i * 256;
        int row = c >> 3, ch = c & 7;
        uint32_t off = row * 128 + ch * 16;
        a_soff[i] = sw128(off);
        b_soff[i] = sw128(off);
        a_g[i] = (const char*)(A + (size_t)(m0 + row) * GK + ch * 8);
        b_g[i] = (const char*)(B + (size_t)(n0 + row) * GK + ch * 8);
    }

    uint32_t rA = wm * 32 + (lane & 7) + ((lane >> 3) & 1) * 8;
    uint32_t kA = ((lane >> 4) & 1) * 16;
    uint32_t rB = wn * 64 + (lane & 7) + ((lane >> 4) & 1) * 8;
    uint32_t kB = ((lane >> 3) & 1) * 16;

    float acc[2][8][4];
#pragma unroll
    for (int mt = 0; mt < 2; mt++)
#pragma unroll
        for (int t = 0; t < 8; t++)
#pragma unroll
            for (int j = 0; j < 4; j++) acc[mt][t][j] = 0.0f;

    const int NS = GK / 64;

#pragma unroll
    for (int s = 0; s < 2; s++) {
        uint32_t ab = sb + SA + s * 16384;
        uint32_t bb = sb + SBB + s * 16384;
        size_t goff = (size_t)s * 128;
#pragma unroll
        for (int i = 0; i < 4; i++) cp16(ab + a_soff[i], a_g[i] + goff);
#pragma unroll
        for (int i = 0; i < 4; i++) cp16(bb + b_soff[i], b_g[i] + goff);
        cp_commit();
    }

    for (int s = 0; s < NS; s++) {
        if (s == NS - 1) cp_wait<0>(); else cp_wait<1>();
        __syncthreads();

        int buf = s & 1;
        uint32_t abase = sb + SA + buf * 16384;
        uint32_t bbase = sb + SBB + buf * 16384;
#pragma unroll
        for (int kk = 0; kk < 4; kk++) {
            uint32_t a[2][4];
#pragma unroll
            for (int mt = 0; mt < 2; mt++) {
                uint32_t off = (rA + mt * 16) * 128 + kk * 32 + kA;
                ldsm4(a[mt][0], a[mt][1], a[mt][2], a[mt][3], abase + sw128(off));
            }
#pragma unroll
            for (int nt = 0; nt < 4; nt++) {
                uint32_t off = (rB + nt * 16) * 128 + kk * 32 + kB;
                uint32_t b0, b1, b2, b3;
                ldsm4(b0, b1, b2, b3, bbase + sw128(off));
                mma16816(acc[0][nt * 2 + 0], a[0], b0, b1);
                mma16816(acc[0][nt * 2 + 1], a[0], b2, b3);
                mma16816(acc[1][nt * 2 + 0], a[1], b0, b1);
                mma16816(acc[1][nt * 2 + 1], a[1], b2, b3);
            }
        }
        __syncthreads();

        if (s + 2 < NS) {
            uint32_t ab = sb + SA + buf * 16384;
            uint32_t bb = sb + SBB + buf * 16384;
            size_t goff = (size_t)(s + 2) * 128;
#pragma unroll
            for (int i = 0; i < 4; i++) cp16(ab + a_soff[i], a_g[i] + goff);
#pragma unroll
            for (int i = 0; i < 4; i++) cp16(bb + b_soff[i], b_g[i] + goff);
            cp_commit();
        }
    }

#pragma unroll
    for (int mt = 0; mt < 2; mt++) {
#pragma unroll
        for (int t = 0; t < 8; t++) {
            int row = m0 + wm * 32 + mt * 16 + (lane >> 2);
            int col = n0 + wn * 64 + t * 8 + (lane & 3) * 2;
            float2 bv = *(const float2*)(bias + col);
            float* p0 = C + (size_t)row * Np + col;
            float2 v0 = { acc[mt][t][0] + bv.x, acc[mt][t][1] + bv.y };
            *(float2*)p0 = v0;
            float* p1 = p0 + 8 * (size_t)Np;
            float2 v1 = { acc[mt][t][2] + bv.x, acc[mt][t][3] + bv.y };
            *(float2*)p1 = v1;
        }
    }
}

// ---------------------------------------------------------------------------
// Flash attention, tf32 HMMA. Pre-converted tf32 operands in smem,
// pair-interleaved layouts so every fragment pair is one float2 LDS.
//
// Interleave: within each 8-col block, col c at position 2*(c&3) + ((c>>2)&1)
// => fragment pair (kc, kc+4) is contiguous.
// Qf/Kf/Pf: [64 rows][68]; Vt: [64 dcols][68] indexed by interleaved krow.
// ---------------------------------------------------------------------------
#define APAD 68
#define ATTN2_SMEM ((4 * 64 * APAD + 64) * 4)   // 69888 B

__device__ __forceinline__ int ilv(int c) {           // interleave within 8-block
    return (c & ~7) + ((c & 3) * 2) + ((c >> 2) & 1);
}

__global__ __launch_bounds__(128)
void attn_tc(const float* __restrict__ qkv,
             const unsigned char* __restrict__ mask,
             float* __restrict__ ctx) {
    extern __shared__ float sm2[];
    float* Qf = sm2;                   // [64][APAD] tf32 bits, col-interleaved
    float* Kf = Qf + 64 * APAD;
    float* Pf = Kf + 64 * APAD;
    float* Vt = Pf + 64 * APAD;        // [dcol][APAD] krow-interleaved
    float* Ms = Vt + 64 * APAD;        // [64]

    int tid = threadIdx.x;
    int lane = tid & 31;
    int w = tid >> 5;
    int b  = blockIdx.y >> 4;
    int h  = blockIdx.y & 15;
    int q0 = blockIdx.x * 64;

    const float* qb = qkv + (size_t)b * Tn * QKVN + h * HDn;
    const float* kb = qb + En;
    const float* vb = qb + 2 * En;

    // ---- load Q (scaled 1/8, tf32, interleaved) ----
#pragma unroll
    for (int it = 0; it < 8; it++) {
        int idx = tid + it * 128;
        int r = idx >> 4;
        int c4 = (idx & 15) * 4;
        float4 v = *(const float4*)(qb + (size_t)(q0 + r) * QKVN + c4);
        int base = r * APAD + (c4 & ~7) + ((c4 & 4) ? 1 : 0);
        Qf[base + 0] = __uint_as_float(f2tf(v.x * 0.125f));
        Qf[base + 2] = __uint_as_float(f2tf(v.y * 0.125f));
        Qf[base + 4] = __uint_as_float(f2tf(v.z * 0.125f));
        Qf[base + 6] = __uint_as_float(f2tf(v.w * 0.125f));
    }

    int r0 = lane >> 2;                // 0..7
    int cq = lane & 3;                 // 0..3
    int pc0 = ilv(2 * cq) & 7;         // interleaved pos of col 2cq in 8-block
    int pc1 = ilv(2 * cq + 1) & 7;

    float oacc[8][4];
#pragma unroll
    for (int n = 0; n < 8; n++)
#pragma unroll
        for (int j = 0; j < 4; j++) oacc[n][j] = 0.0f;
    float m0f = -1e30f, m1f = -1e30f, l0 = 0.0f, l1 = 0.0f;

    // fragment base offsets (float index; all even -> float2-aligned)
    int fa0 = (w * 16 + r0) * APAD + 2 * cq;   // A rows
    int fa1 = fa0 + 8 * APAD;
    int fb  = r0 * APAD + 2 * cq;              // B rows base (add n*8*APAD)

    for (int kv0 = 0; kv0 < Tn; kv0 += 64) {
        // ---- load K (interleaved cols) ----
#pragma unroll
        for (int it = 0; it < 8; it++) {
            int idx = tid + it * 128;
            int r = idx >> 4;
            int c4 = (idx & 15) * 4;
            float4 v = *(const float4*)(kb + (size_t)(kv0 + r) * QKVN + c4);
            int base = r * APAD + (c4 & ~7) + ((c4 & 4) ? 1 : 0);
            Kf[base + 0] = __uint_as_float(f2tf(v.x));
            Kf[base + 2] = __uint_as_float(f2tf(v.y));
            Kf[base + 4] = __uint_as_float(f2tf(v.z));
            Kf[base + 6] = __uint_as_float(f2tf(v.w));
        }
        // ---- load V transposed: Vt[dcol][ilv(krow)] (row-per-lane global) ----
#pragma unroll
        for (int it = 0; it < 8; it++) {
            int idx = tid + it * 128;
            int r = idx & 63;                 // kv row
            int c4 = (idx >> 6) * 4;          // dcol base
            float4 v = *(const float4*)(vb + (size_t)(kv0 + r) * QKVN + c4);
            int pk = ilv(r);
            Vt[(c4 + 0) * APAD + pk] = __uint_as_float(f2tf(v.x));
            Vt[(c4 + 1) * APAD + pk] = __uint_as_float(f2tf(v.y));
            Vt[(c4 + 2) * APAD + pk] = __uint_as_float(f2tf(v.z));
            Vt[(c4 + 3) * APAD + pk] = __uint_as_float(f2tf(v.w));
        }
        if (tid < 64)
            Ms[tid] = mask[b * Tn + kv0 + tid] ? -1e30f : 0.0f;
        __syncthreads();

        // ---- S = Q K^T ----
        float sacc[8][4];
#pragma unroll
        for (int n = 0; n < 8; n++)
#pragma unroll
            for (int j = 0; j < 4; j++) sacc[n][j] = 0.0f;

#pragma unroll
        for (int k = 0; k < 8; k++) {
            float2 pa0 = *(const float2*)&Qf[fa0 + k * 8];
            float2 pa1 = *(const float2*)&Qf[fa1 + k * 8];
            uint32_t a0 = __float_as_uint(pa0.x), a2 = __float_as_uint(pa0.y);
            uint32_t a1 = __float_as_uint(pa1.x), a3 = __float_as_uint(pa1.y);
#pragma unroll
            for (int n = 0; n < 8; n++) {
                float2 pb = *(const float2*)&Kf[fb + n * 8 * APAD + k * 8];
                mma_tf32(sacc[n], a0, a1, a2, a3,
                         __float_as_uint(pb.x), __float_as_uint(pb.y));
            }
        }

        // ---- mask + online softmax (fp32) ----
        float mx0 = -1e30f, mx1 = -1e30f;
#pragma unroll
        for (int n = 0; n < 8; n++) {
            int c = n * 8 + cq * 2;
            float ma = Ms[c], mb2 = Ms[c + 1];
            sacc[n][0] += ma; sacc[n][1] += mb2;
            sacc[n][2] += ma; sacc[n][3] += mb2;
            mx0 = fmaxf(mx0, fmaxf(sacc[n][0], sacc[n][1]));
            mx1 = fmaxf(mx1, fmaxf(sacc[n][2], sacc[n][3]));
        }
        mx0 = fmaxf(mx0, __shfl_xor_sync(0xffffffffu, mx0, 1));
        mx0 = fmaxf(mx0, __shfl_xor_sync(0xffffffffu, mx0, 2));
        mx1 = fmaxf(mx1, __shfl_xor_sync(0xffffffffu, mx1, 1));
        mx1 = fmaxf(mx1, __shfl_xor_sync(0xffffffffu, mx1, 2));

        float nm0 = fmaxf(m0f, mx0), nm1 = fmaxf(m1f, mx1);
        float al0 = __expf(m0f - nm0), al1 = __expf(m1f - nm1);
        float rs0 = 0.0f, rs1 = 0.0f;
#pragma unroll
        for (int n = 0; n < 8; n++) {
            sacc[n][0] = __expf(sacc[n][0] - nm0);
            sacc[n][1] = __expf(sacc[n][1] - nm0);
            sacc[n][2] = __expf(sacc[n][2] - nm1);
            sacc[n][3] = __expf(sacc[n][3] - nm1);
            rs0 += sacc[n][0] + sacc[n][1];
            rs1 += sacc[n][2] + sacc[n][3];
        }
        rs0 += __shfl_xor_sync(0xffffffffu, rs0, 1);
        rs0 += __shfl_xor_sync(0xffffffffu, rs0, 2);
        rs1 += __shfl_xor_sync(0xffffffffu, rs1, 1);
        rs1 += __shfl_xor_sync(0xffffffffu, rs1, 2);

        l0 = l0 * al0 + rs0;  m0f = nm0;
        l1 = l1 * al1 + rs1;  m1f = nm1;
#pragma unroll
        for (int n = 0; n < 8; n++) {
            oacc[n][0] *= al0; oacc[n][1] *= al0;
            oacc[n][2] *= al1; oacc[n][3] *= al1;
        }

        // ---- store P (tf32, interleaved; warp-private rows) ----
        {
            int prow0 = (w * 16 + r0) * APAD;
            int prow1 = prow0 + 8 * APAD;
#pragma unroll
            for (int n = 0; n < 8; n++) {
                int nb = n * 8;
                Pf[prow0 + nb + pc0] = __uint_as_float(f2tf(sacc[n][0]));
                Pf[prow0 + nb + pc1] = __uint_as_float(f2tf(sacc[n][1]));
                Pf[prow1 + nb + pc0] = __uint_as_float(f2tf(sacc[n][2]));
                Pf[prow1 + nb + pc1] = __uint_as_float(f2tf(sacc[n][3]));
            }
        }
        __syncwarp();

        // ---- O += P V ----
#pragma unroll
        for (int k = 0; k < 8; k++) {
            float2 pa0 = *(const float2*)&Pf[fa0 + k * 8];
            float2 pa1 = *(const float2*)&Pf[fa1 + k * 8];
            uint32_t a0 = __float_as_uint(pa0.x), a2 = __float_as_uint(pa0.y);
            uint32_t a1 = __float_as_uint(pa1.x), a3 = __float_as_uint(pa1.y);
#pragma unroll
            for (int n = 0; n < 8; n++) {
                float2 pb = *(const float2*)&Vt[fb + n * 8 * APAD + k * 8];
                mma_tf32(oacc[n], a0, a1, a2, a3,
                         __float_as_uint(pb.x), __float_as_uint(pb.y));
            }
        }
        __syncthreads();
    }

    // ---- epilogue ----
    float inv0 = 1.0f / l0, inv1 = 1.0f / l1;
    int row0 = q0 + w * 16 + r0;
#pragma unroll
    for (int n = 0; n < 8; n++) {
        int col = h * HDn + n * 8 + cq * 2;
        float* p0 = &ctx[((size_t)b * Tn + row0) * En + col];
        *(float2*)p0 = make_float2(oacc[n][0] * inv0, oacc[n][1] * inv0);
        float* p1 = &ctx[((size_t)b * Tn + row0 + 8) * En + col];
        *(float2*)p1 = make_float2(oacc[n][2] * inv1, oacc[n][3] * inv1);
    }
}

// ---------------------------------------------------------------------------
extern "C" void kernel_launch(void* const* d_in, const int* in_sizes, int n_in,
                              void* d_out, int out_size) {
    const float*         x      = (const float*)d_in[0];
    const unsigned char* mask   = (const unsigned char*)d_in[1];
    const float*         qkv_w  = (const float*)d_in[2];
    const float*         qkv_b  = (const float*)d_in[3];
    const float*         proj_w = (const float*)d_in[4];
    const float*         proj_b = (const float*)d_in[5];
    float*               out    = (float*)d_out;

    float *qkv_s, *ctx_s;
    __nv_bfloat16 *xs, *ws, *cs, *pws;
    cudaGetSymbolAddress((void**)&qkv_s, g_qkv);
    cudaGetSymbolAddress((void**)&ctx_s, g_ctx);
    cudaGetSymbolAddress((void**)&xs,  g_xs);
    cudaGetSymbolAddress((void**)&ws,  g_ws);
    cudaGetSymbolAddress((void**)&cs,  g_cs);
    cudaGetSymbolAddress((void**)&pws, g_pws);

    cudaFuncSetAttribute(gemm_hmma,
                         cudaFuncAttributeMaxDynamicSharedMemorySize, GEMM_SMEM);
    cudaFuncSetAttribute(attn_tc,
                         cudaFuncAttributeMaxDynamicSharedMemorySize, ATTN2_SMEM);

    // 1) split x and qkv_w into bf16x3
    split3_kernel<<<(size_t)Mn * En / 4 / 256, 256>>>(x, xs, 1);
    split3_kernel<<<(size_t)QKVN * En / 4 / 256, 256>>>(qkv_w, ws, 2);

    // 2) QKV GEMM
    {
        dim3 grid(QKVN / 128, Mn / 128);
        gemm_hmma<<<grid, 256, GEMM_SMEM>>>(xs, ws, qkv_b, qkv_s, QKVN);
    }

    // 3) attention (tf32 tensor cores)
    {
        dim3 grid(Tn / 64, Bn * Hn);
        attn_tc<<<grid, 128, ATTN2_SMEM>>>(qkv_s, mask, ctx_s);
    }

    // 4) split ctx and proj_w
    split3_kernel<<<(size_t)Mn * En / 4 / 256, 256>>>(ctx_s, cs, 1);
    split3_kernel<<<(size_t)En * En / 4 / 256, 256>>>(proj_w, pws, 2);

    // 5) proj GEMM
    {
        dim3 grid(En / 128, Mn / 128);
        gemm_hmma<<<grid, 256, GEMM_SMEM>>>(cs, pws, proj_b, out, En);
    }
}

// round 8
// speedup vs baseline: 1.4613x; 1.4613x over previous
#include <cuda_runtime.h>
#include <cuda_bf16.h>
#include <stdint.h>
#include <math.h>

#define Bn   4
#define Tn   2048
#define En   1024
#define Hn   16
#define HDn  64
#define Mn   (Bn * Tn)          // 8192
#define QKVN (3 * En)           // 3072
#define GK   3072               // split K' = 3*E for bf16x3 trick

// ---------------- scratch (__device__ globals; no cudaMalloc allowed) -------
__device__ float g_qkv[(size_t)Mn * QKVN];            // 96 MB fp32
__device__ float g_ctx[(size_t)Mn * En];              // 32 MB fp32
__device__ __nv_bfloat16 g_xs [(size_t)Mn * GK];      // 48 MB  x split
__device__ __nv_bfloat16 g_ws [(size_t)QKVN * GK];    // 18 MB  qkv_w split
__device__ __nv_bfloat16 g_cs [(size_t)Mn * GK];      // 48 MB  ctx split
__device__ __nv_bfloat16 g_pws[(size_t)En * GK];      //  6 MB  proj_w split

// ---------------- helpers (sm_80/90 feature set only) -----------------------
__device__ __forceinline__ uint32_t smem_u32(const void* p) {
    uint32_t a;
    asm("{ .reg .u64 t; cvta.to.shared.u64 t, %1; cvt.u32.u64 %0, t; }"
        : "=r"(a) : "l"(p));
    return a;
}
__device__ __forceinline__ void cp16(uint32_t saddr, const void* g) {
    asm volatile("cp.async.cg.shared.global [%0], [%1], 16;"
                 :: "r"(saddr), "l"(g));
}
template <int N>
__device__ __forceinline__ void cp_wait() {
    asm volatile("cp.async.wait_group %0;" :: "n"(N) : "memory");
}
__device__ __forceinline__ void cp_commit() {
    asm volatile("cp.async.commit_group;" ::: "memory");
}
__device__ __forceinline__ void ldsm4(uint32_t& r0, uint32_t& r1,
                                      uint32_t& r2, uint32_t& r3,
                                      uint32_t addr) {
    asm volatile("ldmatrix.sync.aligned.m8n8.x4.shared.b16 {%0,%1,%2,%3}, [%4];"
                 : "=r"(r0), "=r"(r1), "=r"(r2), "=r"(r3) : "r"(addr));
}
__device__ __forceinline__ void mma16816(float* d, const uint32_t* a,
                                         uint32_t b0, uint32_t b1) {
    asm volatile(
        "mma.sync.aligned.m16n8k16.row.col.f32.bf16.bf16.f32 "
        "{%0,%1,%2,%3}, {%4,%5,%6,%7}, {%8,%9}, {%0,%1,%2,%3};"
        : "+f"(d[0]), "+f"(d[1]), "+f"(d[2]), "+f"(d[3])
        : "r"(a[0]), "r"(a[1]), "r"(a[2]), "r"(a[3]), "r"(b0), "r"(b1));
}
__device__ __forceinline__ uint32_t sw128(uint32_t off) {
    return off ^ ((off >> 3) & 0x70);
}
// tf32 helpers
__device__ __forceinline__ uint32_t f2tf(float x) {
    uint32_t r;
    asm("cvt.rna.tf32.f32 %0, %1;" : "=r"(r) : "f"(x));
    return r;
}
__device__ __forceinline__ float f2tf_f(float x) {
    return __uint_as_float(f2tf(x));
}
__device__ __forceinline__ void mma_tf32(float* d, uint32_t a0, uint32_t a1,
                                         uint32_t a2, uint32_t a3,
                                         uint32_t b0, uint32_t b1) {
    asm volatile(
        "mma.sync.aligned.m16n8k8.row.col.f32.tf32.tf32.f32 "
        "{%0,%1,%2,%3}, {%4,%5,%6,%7}, {%8,%9}, {%0,%1,%2,%3};"
        : "+f"(d[0]), "+f"(d[1]), "+f"(d[2]), "+f"(d[3])
        : "r"(a0), "r"(a1), "r"(a2), "r"(a3), "r"(b0), "r"(b1));
}

// ---------------------------------------------------------------------------
// bf16x3 split conversion
// ---------------------------------------------------------------------------
struct bf16x4 { __nv_bfloat162 a, b; };

__global__ void split3_kernel(const float* __restrict__ in,
                              __nv_bfloat16* __restrict__ out, int lo_sec) {
    size_t i = ((size_t)blockIdx.x * blockDim.x + threadIdx.x) * 4;
    size_t row = i >> 10;          // K = 1024
    int col = (int)(i & 1023);
    float4 v = *(const float4*)(in + i);
    float xs[4] = {v.x, v.y, v.z, v.w};
    __nv_bfloat16 h[4], l[4];
#pragma unroll
    for (int j = 0; j < 4; j++) {
        h[j] = __float2bfloat16_rn(xs[j]);
        l[j] = __float2bfloat16_rn(xs[j] - __bfloat162float(h[j]));
    }
    bf16x4 hv, lv;
    hv.a = __nv_bfloat162(h[0], h[1]); hv.b = __nv_bfloat162(h[2], h[3]);
    lv.a = __nv_bfloat162(l[0], l[1]); lv.b = __nv_bfloat162(l[2], l[3]);
    __nv_bfloat16* o = out + row * GK;
    *(bf16x4*)(o + col) = hv;
    *(bf16x4*)(o + (3 - lo_sec) * 1024 + col) = hv;
    *(bf16x4*)(o + lo_sec * 1024 + col) = lv;
}

// ---------------------------------------------------------------------------
// HMMA bf16 GEMM (verified round 4)
// ---------------------------------------------------------------------------
#define GEMM_SMEM 65536

__global__ __launch_bounds__(256, 2)
void gemm_hmma(const __nv_bfloat16* __restrict__ A,
               const __nv_bfloat16* __restrict__ B,
               const float* __restrict__ bias,
               float* __restrict__ C, int Np) {
    extern __shared__ char gsm[];
    uint32_t sb = smem_u32(gsm);
    const uint32_t SA = 0, SBB = 32768;

    int tid = threadIdx.x;
    int lane = tid & 31;
    int wid = tid >> 5;
    int wm = wid & 3;
    int wn = wid >> 2;
    int m0 = blockIdx.y * 128;
    int n0 = blockIdx.x * 128;

    uint32_t a_soff[4]; const char* a_g[4];
    uint32_t b_soff[4]; const char* b_g[4];
#pragma unroll
    for (int i = 0; i < 4; i++) {
        int c = tid + i * 256;
        int row = c >> 3, ch = c & 7;
        uint32_t off = row * 128 + ch * 16;
        a_soff[i] = sw128(off);
        b_soff[i] = sw128(off);
        a_g[i] = (const char*)(A + (size_t)(m0 + row) * GK + ch * 8);
        b_g[i] = (const char*)(B + (size_t)(n0 + row) * GK + ch * 8);
    }

    uint32_t rA = wm * 32 + (lane & 7) + ((lane >> 3) & 1) * 8;
    uint32_t kA = ((lane >> 4) & 1) * 16;
    uint32_t rB = wn * 64 + (lane & 7) + ((lane >> 4) & 1) * 8;
    uint32_t kB = ((lane >> 3) & 1) * 16;

    float acc[2][8][4];
#pragma unroll
    for (int mt = 0; mt < 2; mt++)
#pragma unroll
        for (int t = 0; t < 8; t++)
#pragma unroll
            for (int j = 0; j < 4; j++) acc[mt][t][j] = 0.0f;

    const int NS = GK / 64;

#pragma unroll
    for (int s = 0; s < 2; s++) {
        uint32_t ab = sb + SA + s * 16384;
        uint32_t bb = sb + SBB + s * 16384;
        size_t goff = (size_t)s * 128;
#pragma unroll
        for (int i = 0; i < 4; i++) cp16(ab + a_soff[i], a_g[i] + goff);
#pragma unroll
        for (int i = 0; i < 4; i++) cp16(bb + b_soff[i], b_g[i] + goff);
        cp_commit();
    }

    for (int s = 0; s < NS; s++) {
        if (s == NS - 1) cp_wait<0>(); else cp_wait<1>();
        __syncthreads();

        int buf = s & 1;
        uint32_t abase = sb + SA + buf * 16384;
        uint32_t bbase = sb + SBB + buf * 16384;
#pragma unroll
        for (int kk = 0; kk < 4; kk++) {
            uint32_t a[2][4];
#pragma unroll
            for (int mt = 0; mt < 2; mt++) {
                uint32_t off = (rA + mt * 16) * 128 + kk * 32 + kA;
                ldsm4(a[mt][0], a[mt][1], a[mt][2], a[mt][3], abase + sw128(off));
            }
#pragma unroll
            for (int nt = 0; nt < 4; nt++) {
                uint32_t off = (rB + nt * 16) * 128 + kk * 32 + kB;
                uint32_t b0, b1, b2, b3;
                ldsm4(b0, b1, b2, b3, bbase + sw128(off));
                mma16816(acc[0][nt * 2 + 0], a[0], b0, b1);
                mma16816(acc[0][nt * 2 + 1], a[0], b2, b3);
                mma16816(acc[1][nt * 2 + 0], a[1], b0, b1);
                mma16816(acc[1][nt * 2 + 1], a[1], b2, b3);
            }
        }
        __syncthreads();

        if (s + 2 < NS) {
            uint32_t ab = sb + SA + buf * 16384;
            uint32_t bb = sb + SBB + buf * 16384;
            size_t goff = (size_t)(s + 2) * 128;
#pragma unroll
            for (int i = 0; i < 4; i++) cp16(ab + a_soff[i], a_g[i] + goff);
#pragma unroll
            for (int i = 0; i < 4; i++) cp16(bb + b_soff[i], b_g[i] + goff);
            cp_commit();
        }
    }

#pragma unroll
    for (int mt = 0; mt < 2; mt++) {
#pragma unroll
        for (int t = 0; t < 8; t++) {
            int row = m0 + wm * 32 + mt * 16 + (lane >> 2);
            int col = n0 + wn * 64 + t * 8 + (lane & 3) * 2;
            float2 bv = *(const float2*)(bias + col);
            float* p0 = C + (size_t)row * Np + col;
            float2 v0 = { acc[mt][t][0] + bv.x, acc[mt][t][1] + bv.y };
            *(float2*)p0 = v0;
            float* p1 = p0 + 8 * (size_t)Np;
            float2 v1 = { acc[mt][t][2] + bv.x, acc[mt][t][3] + bv.y };
            *(float2*)p1 = v1;
        }
    }
}

// ---------------------------------------------------------------------------
// Flash attention, tf32 HMMA. Round-6 layout (scalar LDS, conflict-free),
// with operands PRE-CONVERTED to tf32 at smem fill (cvt count 320->96/tile;
// numerics bit-identical to round 6).
// ---------------------------------------------------------------------------
#define APAD 68
#define VPAD 72
#define ATTN2_SMEM ((64 * (3 * APAD) + 64 * VPAD + 64) * 4)   // 70912 B

__global__ __launch_bounds__(128)
void attn_tc(const float* __restrict__ qkv,
             const unsigned char* __restrict__ mask,
             float* __restrict__ ctx) {
    extern __shared__ float sm2[];
    float* Qs = sm2;                   // [64][APAD] tf32 bits
    float* Ks = Qs + 64 * APAD;        // [64][APAD] tf32 bits
    float* Ps = Ks + 64 * APAD;        // [64][APAD] tf32 bits
    float* Vs = Ps + 64 * APAD;        // [64][VPAD] tf32 bits
    float* Ms = Vs + 64 * VPAD;        // [64]

    int tid = threadIdx.x;
    int lane = tid & 31;
    int w = tid >> 5;                  // warp 0..3
    int b  = blockIdx.y >> 4;
    int h  = blockIdx.y & 15;
    int q0 = blockIdx.x * 64;

    const float* qb = qkv + (size_t)b * Tn * QKVN + h * HDn;
    const float* kb = qb + En;
    const float* vb = qb + 2 * En;

    // load Q tile (scaled by 1/8, converted to tf32 once)
#pragma unroll
    for (int it = 0; it < 8; it++) {
        int idx = tid + it * 128;      // 0..1023
        int r = idx >> 4;
        int c4 = (idx & 15) * 4;
        float4 v = *(const float4*)(qb + (size_t)(q0 + r) * QKVN + c4);
        Qs[r * APAD + c4 + 0] = f2tf_f(v.x * 0.125f);
        Qs[r * APAD + c4 + 1] = f2tf_f(v.y * 0.125f);
        Qs[r * APAD + c4 + 2] = f2tf_f(v.z * 0.125f);
        Qs[r * APAD + c4 + 3] = f2tf_f(v.w * 0.125f);
    }

    int r0 = lane >> 2;                // 0..7
    int cq = lane & 3;                 // quad col

    float oacc[8][4];
#pragma unroll
    for (int n = 0; n < 8; n++)
#pragma unroll
        for (int j = 0; j < 4; j++) oacc[n][j] = 0.0f;
    float m0f = -1e30f, m1f = -1e30f, l0 = 0.0f, l1 = 0.0f;

    for (int kv0 = 0; kv0 < Tn; kv0 += 64) {
        // load K, V tiles (tf32 at fill) + mask
#pragma unroll
        for (int it = 0; it < 8; it++) {
            int idx = tid + it * 128;
            int r = idx >> 4;
            int c4 = (idx & 15) * 4;
            float4 kv = *(const float4*)(kb + (size_t)(kv0 + r) * QKVN + c4);
            Ks[r * APAD + c4 + 0] = f2tf_f(kv.x);
            Ks[r * APAD + c4 + 1] = f2tf_f(kv.y);
            Ks[r * APAD + c4 + 2] = f2tf_f(kv.z);
            Ks[r * APAD + c4 + 3] = f2tf_f(kv.w);
            float4 vv = *(const float4*)(vb + (size_t)(kv0 + r) * QKVN + c4);
            Vs[r * VPAD + c4 + 0] = f2tf_f(vv.x);
            Vs[r * VPAD + c4 + 1] = f2tf_f(vv.y);
            Vs[r * VPAD + c4 + 2] = f2tf_f(vv.z);
            Vs[r * VPAD + c4 + 3] = f2tf_f(vv.w);
        }
        if (tid < 64)
            Ms[tid] = mask[b * Tn + kv0 + tid] ? -1e30f : 0.0f;
        __syncthreads();

        // ---- S = Q K^T  (tf32 mma; operands already tf32 bits) ----
        float sacc[8][4];
#pragma unroll
        for (int n = 0; n < 8; n++)
#pragma unroll
            for (int j = 0; j < 4; j++) sacc[n][j] = 0.0f;

#pragma unroll
        for (int k = 0; k < 8; k++) {
            int kc = k * 8 + cq;
            uint32_t a0 = __float_as_uint(Qs[(w * 16 + r0) * APAD + kc]);
            uint32_t a1 = __float_as_uint(Qs[(w * 16 + r0 + 8) * APAD + kc]);
            uint32_t a2 = __float_as_uint(Qs[(w * 16 + r0) * APAD + kc + 4]);
            uint32_t a3 = __float_as_uint(Qs[(w * 16 + r0 + 8) * APAD + kc + 4]);
#pragma unroll
            for (int n = 0; n < 8; n++) {
                int krow = n * 8 + r0;
                uint32_t b0 = __float_as_uint(Ks[krow * APAD + kc]);
                uint32_t b1 = __float_as_uint(Ks[krow * APAD + kc + 4]);
                mma_tf32(sacc[n], a0, a1, a2, a3, b0, b1);
            }
        }

        // ---- mask + online softmax (fp32) ----
        float mx0 = -1e30f, mx1 = -1e30f;
#pragma unroll
        for (int n = 0; n < 8; n++) {
            int c = n * 8 + cq * 2;
            float ma = Ms[c], mb2 = Ms[c + 1];
            sacc[n][0] += ma; sacc[n][1] += mb2;
            sacc[n][2] += ma; sacc[n][3] += mb2;
            mx0 = fmaxf(mx0, fmaxf(sacc[n][0], sacc[n][1]));
            mx1 = fmaxf(mx1, fmaxf(sacc[n][2], sacc[n][3]));
        }
        mx0 = fmaxf(mx0, __shfl_xor_sync(0xffffffffu, mx0, 1));
        mx0 = fmaxf(mx0, __shfl_xor_sync(0xffffffffu, mx0, 2));
        mx1 = fmaxf(mx1, __shfl_xor_sync(0xffffffffu, mx1, 1));
        mx1 = fmaxf(mx1, __shfl_xor_sync(0xffffffffu, mx1, 2));

        float nm0 = fmaxf(m0f, mx0), nm1 = fmaxf(m1f, mx1);
        float al0 = __expf(m0f - nm0), al1 = __expf(m1f - nm1);
        float rs0 = 0.0f, rs1 = 0.0f;
#pragma unroll
        for (int n = 0; n < 8; n++) {
            sacc[n][0] = __expf(sacc[n][0] - nm0);
            sacc[n][1] = __expf(sacc[n][1] - nm0);
            sacc[n][2] = __expf(sacc[n][2] - nm1);
            sacc[n][3] = __expf(sacc[n][3] - nm1);
            rs0 += sacc[n][0] + sacc[n][1];
            rs1 += sacc[n][2] + sacc[n][3];
        }
        rs0 += __shfl_xor_sync(0xffffffffu, rs0, 1);
        rs0 += __shfl_xor_sync(0xffffffffu, rs0, 2);
        rs1 += __shfl_xor_sync(0xffffffffu, rs1, 1);
        rs1 += __shfl_xor_sync(0xffffffffu, rs1, 2);

        l0 = l0 * al0 + rs0;  m0f = nm0;
        l1 = l1 * al1 + rs1;  m1f = nm1;
#pragma unroll
        for (int n = 0; n < 8; n++) {
            oacc[n][0] *= al0; oacc[n][1] *= al0;
            oacc[n][2] *= al1; oacc[n][3] *= al1;
        }

        // ---- store P (tf32 at store; warp-private rows) ----
#pragma unroll
        for (int n = 0; n < 8; n++) {
            int c = n * 8 + cq * 2;
            Ps[(w * 16 + r0) * APAD + c + 0] = f2tf_f(sacc[n][0]);
            Ps[(w * 16 + r0) * APAD + c + 1] = f2tf_f(sacc[n][1]);
            Ps[(w * 16 + r0 + 8) * APAD + c + 0] = f2tf_f(sacc[n][2]);
            Ps[(w * 16 + r0 + 8) * APAD + c + 1] = f2tf_f(sacc[n][3]);
        }
        __syncwarp();

        // ---- O += P V ----
#pragma unroll
        for (int k = 0; k < 8; k++) {
            int kc = k * 8 + cq;
            uint32_t a0 = __float_as_uint(Ps[(w * 16 + r0) * APAD + kc]);
            uint32_t a1 = __float_as_uint(Ps[(w * 16 + r0 + 8) * APAD + kc]);
            uint32_t a2 = __float_as_uint(Ps[(w * 16 + r0) * APAD + kc + 4]);
            uint32_t a3 = __float_as_uint(Ps[(w * 16 + r0 + 8) * APAD + kc + 4]);
#pragma unroll
            for (int n = 0; n < 8; n++) {
                int dcol = n * 8 + r0;
                uint32_t b0 = __float_as_uint(Vs[(k * 8 + cq) * VPAD + dcol]);
                uint32_t b1 = __float_as_uint(Vs[(k * 8 + cq + 4) * VPAD + dcol]);
                mma_tf32(oacc[n], a0, a1, a2, a3, b0, b1);
            }
        }
        __syncthreads();
    }

    // epilogue
    float inv0 = 1.0f / l0, inv1 = 1.0f / l1;
    int row0 = q0 + w * 16 + r0;
#pragma unroll
    for (int n = 0; n < 8; n++) {
        int col = h * HDn + n * 8 + cq * 2;
        float* p0 = &ctx[((size_t)b * Tn + row0) * En + col];
        *(float2*)p0 = make_float2(oacc[n][0] * inv0, oacc[n][1] * inv0);
        float* p1 = &ctx[((size_t)b * Tn + row0 + 8) * En + col];
        *(float2*)p1 = make_float2(oacc[n][2] * inv1, oacc[n][3] * inv1);
    }
}

// ---------------------------------------------------------------------------
extern "C" void kernel_launch(void* const* d_in, const int* in_sizes, int n_in,
                              void* d_out, int out_size) {
    const float*         x      = (const float*)d_in[0];
    const unsigned char* mask   = (const unsigned char*)d_in[1];
    const float*         qkv_w  = (const float*)d_in[2];
    const float*         qkv_b  = (const float*)d_in[3];
    const float*         proj_w = (const float*)d_in[4];
    const float*         proj_b = (const float*)d_in[5];
    float*               out    = (float*)d_out;

    float *qkv_s, *ctx_s;
    __nv_bfloat16 *xs, *ws, *cs, *pws;
    cudaGetSymbolAddress((void**)&qkv_s, g_qkv);
    cudaGetSymbolAddress((void**)&ctx_s, g_ctx);
    cudaGetSymbolAddress((void**)&xs,  g_xs);
    cudaGetSymbolAddress((void**)&ws,  g_ws);
    cudaGetSymbolAddress((void**)&cs,  g_cs);
    cudaGetSymbolAddress((void**)&pws, g_pws);

    cudaFuncSetAttribute(gemm_hmma,
                         cudaFuncAttributeMaxDynamicSharedMemorySize, GEMM_SMEM);
    cudaFuncSetAttribute(attn_tc,
                         cudaFuncAttributeMaxDynamicSharedMemorySize, ATTN2_SMEM);

    // 1) split x and qkv_w into bf16x3
    split3_kernel<<<(size_t)Mn * En / 4 / 256, 256>>>(x, xs, 1);
    split3_kernel<<<(size_t)QKVN * En / 4 / 256, 256>>>(qkv_w, ws, 2);

    // 2) QKV GEMM
    {
        dim3 grid(QKVN / 128, Mn / 128);
        gemm_hmma<<<grid, 256, GEMM_SMEM>>>(xs, ws, qkv_b, qkv_s, QKVN);
    }

    // 3) attention (tf32 tensor cores)
    {
        dim3 grid(Tn / 64, Bn * Hn);
        attn_tc<<<grid, 128, ATTN2_SMEM>>>(qkv_s, mask, ctx_s);
    }

    // 4) split ctx and proj_w
    split3_kernel<<<(size_t)Mn * En / 4 / 256, 256>>>(ctx_s, cs, 1);
    split3_kernel<<<(size_t)En * En / 4 / 256, 256>>>(proj_w, pws, 2);

    // 5) proj GEMM
    {
        dim3 grid(En / 128, Mn / 128);
        gemm_hmma<<<grid, 256, GEMM_SMEM>>>(cs, pws, proj_b, out, En);
    }
}

// round 9
// speedup vs baseline: 1.4815x; 1.0138x over previous
#include <cuda_runtime.h>
#include <cuda_bf16.h>
#include <stdint.h>
#include <math.h>

#define Bn   4
#define Tn   2048
#define En   1024
#define Hn   16
#define HDn  64
#define Mn   (Bn * Tn)          // 8192
#define QKVN (3 * En)           // 3072
#define GK   3072               // split K' = 3*E for bf16x3 trick

// ---------------- scratch (__device__ globals; no cudaMalloc allowed) -------
__device__ float g_qkv[(size_t)Mn * QKVN];            // 96 MB fp32
__device__ float g_ctx[(size_t)Mn * En];              // 32 MB fp32
__device__ __nv_bfloat16 g_xs [(size_t)Mn * GK];      // 48 MB  x split
__device__ __nv_bfloat16 g_ws [(size_t)QKVN * GK];    // 18 MB  qkv_w split
__device__ __nv_bfloat16 g_cs [(size_t)Mn * GK];      // 48 MB  ctx split
__device__ __nv_bfloat16 g_pws[(size_t)En * GK];      //  6 MB  proj_w split

// ---------------- helpers (sm_80/90 feature set only) -----------------------
__device__ __forceinline__ uint32_t smem_u32(const void* p) {
    uint32_t a;
    asm("{ .reg .u64 t; cvta.to.shared.u64 t, %1; cvt.u32.u64 %0, t; }"
        : "=r"(a) : "l"(p));
    return a;
}
__device__ __forceinline__ void cp16(uint32_t saddr, const void* g) {
    asm volatile("cp.async.cg.shared.global [%0], [%1], 16;"
                 :: "r"(saddr), "l"(g));
}
template <int N>
__device__ __forceinline__ void cp_wait() {
    asm volatile("cp.async.wait_group %0;" :: "n"(N) : "memory");
}
__device__ __forceinline__ void cp_commit() {
    asm volatile("cp.async.commit_group;" ::: "memory");
}
__device__ __forceinline__ void ldsm4(uint32_t& r0, uint32_t& r1,
                                      uint32_t& r2, uint32_t& r3,
                                      uint32_t addr) {
    asm volatile("ldmatrix.sync.aligned.m8n8.x4.shared.b16 {%0,%1,%2,%3}, [%4];"
                 : "=r"(r0), "=r"(r1), "=r"(r2), "=r"(r3) : "r"(addr));
}
__device__ __forceinline__ void ldsm2(uint32_t& r0, uint32_t& r1,
                                      uint32_t addr) {
    asm volatile("ldmatrix.sync.aligned.m8n8.x2.shared.b16 {%0,%1}, [%2];"
                 : "=r"(r0), "=r"(r1) : "r"(addr));
}
__device__ __forceinline__ void mma16816(float* d, const uint32_t* a,
                                         uint32_t b0, uint32_t b1) {
    asm volatile(
        "mma.sync.aligned.m16n8k16.row.col.f32.bf16.bf16.f32 "
        "{%0,%1,%2,%3}, {%4,%5,%6,%7}, {%8,%9}, {%0,%1,%2,%3};"
        : "+f"(d[0]), "+f"(d[1]), "+f"(d[2]), "+f"(d[3])
        : "r"(a[0]), "r"(a[1]), "r"(a[2]), "r"(a[3]), "r"(b0), "r"(b1));
}
__device__ __forceinline__ uint32_t sw128(uint32_t off) {
    return off ^ ((off >> 3) & 0x70);
}
// tf32 helpers
__device__ __forceinline__ uint32_t f2tf(float x) {
    uint32_t r;
    asm("cvt.rna.tf32.f32 %0, %1;" : "=r"(r) : "f"(x));
    return r;
}
__device__ __forceinline__ float f2tf_f(float x) {
    return __uint_as_float(f2tf(x));
}
__device__ __forceinline__ void mma_tf32(float* d, uint32_t a0, uint32_t a1,
                                         uint32_t a2, uint32_t a3,
                                         uint32_t b0, uint32_t b1) {
    asm volatile(
        "mma.sync.aligned.m16n8k8.row.col.f32.tf32.tf32.f32 "
        "{%0,%1,%2,%3}, {%4,%5,%6,%7}, {%8,%9}, {%0,%1,%2,%3};"
        : "+f"(d[0]), "+f"(d[1]), "+f"(d[2]), "+f"(d[3])
        : "r"(a0), "r"(a1), "r"(a2), "r"(a3), "r"(b0), "r"(b1));
}

// ---------------------------------------------------------------------------
// bf16x3 split conversion
// ---------------------------------------------------------------------------
struct bf16x4 { __nv_bfloat162 a, b; };

__global__ void split3_kernel(const float* __restrict__ in,
                              __nv_bfloat16* __restrict__ out, int lo_sec) {
    size_t i = ((size_t)blockIdx.x * blockDim.x + threadIdx.x) * 4;
    size_t row = i >> 10;          // K = 1024
    int col = (int)(i & 1023);
    float4 v = *(const float4*)(in + i);
    float xs[4] = {v.x, v.y, v.z, v.w};
    __nv_bfloat16 h[4], l[4];
#pragma unroll
    for (int j = 0; j < 4; j++) {
        h[j] = __float2bfloat16_rn(xs[j]);
        l[j] = __float2bfloat16_rn(xs[j] - __bfloat162float(h[j]));
    }
    bf16x4 hv, lv;
    hv.a = __nv_bfloat162(h[0], h[1]); hv.b = __nv_bfloat162(h[2], h[3]);
    lv.a = __nv_bfloat162(l[0], l[1]); lv.b = __nv_bfloat162(l[2], l[3]);
    __nv_bfloat16* o = out + row * GK;
    *(bf16x4*)(o + col) = hv;
    *(bf16x4*)(o + (3 - lo_sec) * 1024 + col) = hv;
    *(bf16x4*)(o + lo_sec * 1024 + col) = lv;
}

// ---------------------------------------------------------------------------
// HMMA bf16 GEMM (verified round 4)
// ---------------------------------------------------------------------------
#define GEMM_SMEM 65536

__global__ __launch_bounds__(256, 2)
void gemm_hmma(const __nv_bfloat16* __restrict__ A,
               const __nv_bfloat16* __restrict__ B,
               const float* __restrict__ bias,
               float* __restrict__ C, int Np) {
    extern __shared__ char gsm[];
    uint32_t sb = smem_u32(gsm);
    const uint32_t SA = 0, SBB = 32768;

    int tid = threadIdx.x;
    int lane = tid & 31;
    int wid = tid >> 5;
    int wm = wid & 3;
    int wn = wid >> 2;
    int m0 = blockIdx.y * 128;
    int n0 = blockIdx.x * 128;

    uint32_t a_soff[4]; const char* a_g[4];
    uint32_t b_soff[4]; const char* b_g[4];
#pragma unroll
    for (int i = 0; i < 4; i++) {
        int c = tid + i * 256;
        int row = c >> 3, ch = c & 7;
        uint32_t off = row * 128 + ch * 16;
        a_soff[i] = sw128(off);
        b_soff[i] = sw128(off);
        a_g[i] = (const char*)(A + (size_t)(m0 + row) * GK + ch * 8);
        b_g[i] = (const char*)(B + (size_t)(n0 + row) * GK + ch * 8);
    }

    uint32_t rA = wm * 32 + (lane & 7) + ((lane >> 3) & 1) * 8;
    uint32_t kA = ((lane >> 4) & 1) * 16;
    uint32_t rB = wn * 64 + (lane & 7) + ((lane >> 4) & 1) * 8;
    uint32_t kB = ((lane >> 3) & 1) * 16;

    float acc[2][8][4];
#pragma unroll
    for (int mt = 0; mt < 2; mt++)
#pragma unroll
        for (int t = 0; t < 8; t++)
#pragma unroll
            for (int j = 0; j < 4; j++) acc[mt][t][j] = 0.0f;

    const int NS = GK / 64;

#pragma unroll
    for (int s = 0; s < 2; s++) {
        uint32_t ab = sb + SA + s * 16384;
        uint32_t bb = sb + SBB + s * 16384;
        size_t goff = (size_t)s * 128;
#pragma unroll
        for (int i = 0; i < 4; i++) cp16(ab + a_soff[i], a_g[i] + goff);
#pragma unroll
        for (int i = 0; i < 4; i++) cp16(bb + b_soff[i], b_g[i] + goff);
        cp_commit();
    }

    for (int s = 0; s < NS; s++) {
        if (s == NS - 1) cp_wait<0>(); else cp_wait<1>();
        __syncthreads();

        int buf = s & 1;
        uint32_t abase = sb + SA + buf * 16384;
        uint32_t bbase = sb + SBB + buf * 16384;
#pragma unroll
        for (int kk = 0; kk < 4; kk++) {
            uint32_t a[2][4];
#pragma unroll
            for (int mt = 0; mt < 2; mt++) {
                uint32_t off = (rA + mt * 16) * 128 + kk * 32 + kA;
                ldsm4(a[mt][0], a[mt][1], a[mt][2], a[mt][3], abase + sw128(off));
            }
#pragma unroll
            for (int nt = 0; nt < 4; nt++) {
                uint32_t off = (rB + nt * 16) * 128 + kk * 32 + kB;
                uint32_t b0, b1, b2, b3;
                ldsm4(b0, b1, b2, b3, bbase + sw128(off));
                mma16816(acc[0][nt * 2 + 0], a[0], b0, b1);
                mma16816(acc[0][nt * 2 + 1], a[0], b2, b3);
                mma16816(acc[1][nt * 2 + 0], a[1], b0, b1);
                mma16816(acc[1][nt * 2 + 1], a[1], b2, b3);
            }
        }
        __syncthreads();

        if (s + 2 < NS) {
            uint32_t ab = sb + SA + buf * 16384;
            uint32_t bb = sb + SBB + buf * 16384;
            size_t goff = (size_t)(s + 2) * 128;
#pragma unroll
            for (int i = 0; i < 4; i++) cp16(ab + a_soff[i], a_g[i] + goff);
#pragma unroll
            for (int i = 0; i < 4; i++) cp16(bb + b_soff[i], b_g[i] + goff);
            cp_commit();
        }
    }

#pragma unroll
    for (int mt = 0; mt < 2; mt++) {
#pragma unroll
        for (int t = 0; t < 8; t++) {
            int row = m0 + wm * 32 + mt * 16 + (lane >> 2);
            int col = n0 + wn * 64 + t * 8 + (lane & 3) * 2;
            float2 bv = *(const float2*)(bias + col);
            float* p0 = C + (size_t)row * Np + col;
            float2 v0 = { acc[mt][t][0] + bv.x, acc[mt][t][1] + bv.y };
            *(float2*)p0 = v0;
            float* p1 = p0 + 8 * (size_t)Np;
            float2 v1 = { acc[mt][t][2] + bv.x, acc[mt][t][3] + bv.y };
            *(float2*)p1 = v1;
        }
    }
}

// ---------------------------------------------------------------------------
// Flash attention, tf32 HMMA, ldmatrix fragments, warp M-tile = 32 rows.
// Block = 128 threads / 4 warps = 128 q rows; KV tiles of 64.
// smem: Qs[128][68], Ks[64][68], Ps[128][68], Vt[64][68] (V transposed), Ms[64]
// tf32 stored in smem (converted at fill). ldmatrix treats each m8n8.b16 tile
// as an 8x4 matrix of 32-bit tf32: lane l gets element (l>>2, l&3) == (r0,cq).
// ---------------------------------------------------------------------------
#define APAD 68
#define ATTN3_SMEM ((128 * APAD + 64 * APAD + 128 * APAD + 64 * APAD + 64) * 4)

__global__ __launch_bounds__(128)
void attn_tc(const float* __restrict__ qkv,
             const unsigned char* __restrict__ mask,
             float* __restrict__ ctx) {
    extern __shared__ float sm2[];
    float* Qs = sm2;                    // [128][APAD]
    float* Ks = Qs + 128 * APAD;        // [64][APAD]
    float* Ps = Ks + 64 * APAD;         // [128][APAD]
    float* Vt = Ps + 128 * APAD;        // [64][APAD]  Vt[d][kv]
    float* Ms = Vt + 64 * APAD;         // [64]

    int tid = threadIdx.x;
    int lane = tid & 31;
    int w = tid >> 5;
    int b  = blockIdx.y >> 4;
    int h  = blockIdx.y & 15;
    int q0 = blockIdx.x * 128;
    int wrow = w * 32;

    const float* qb = qkv + (size_t)b * Tn * QKVN + h * HDn;
    const float* kb = qb + En;
    const float* vb = qb + 2 * En;

    // ---- Q fill: 128 rows, scaled 1/8, tf32 ----
#pragma unroll
    for (int it = 0; it < 16; it++) {
        int idx = tid + it * 128;          // 0..2047
        int r = idx >> 4;
        int c4 = (idx & 15) * 4;
        float4 v = *(const float4*)(qb + (size_t)(q0 + r) * QKVN + c4);
        v.x = f2tf_f(v.x * 0.125f); v.y = f2tf_f(v.y * 0.125f);
        v.z = f2tf_f(v.z * 0.125f); v.w = f2tf_f(v.w * 0.125f);
        *(float4*)&Qs[r * APAD + c4] = v;
    }

    int r0 = lane >> 2;
    int cq = lane & 3;

    // ldmatrix per-lane addresses (bytes)
    uint32_t sb = smem_u32(sm2);
    int t  = lane >> 3;                       // 0..3
    int arow = (t & 1) * 8 + (lane & 7);
    int acol = (t >> 1) * 4;
    uint32_t qs_a = sb + (uint32_t)(((wrow + arow) * APAD + acol) * 4);
    uint32_t ps_a = sb + (uint32_t)((128 * APAD + 64 * APAD) * 4)
                       + (uint32_t)(((wrow + arow) * APAD + acol) * 4);
    int brow = lane & 7;
    int bsel = (lane >> 3) & 1;
    uint32_t ks_b = sb + (uint32_t)((128 * APAD) * 4)
                       + (uint32_t)((brow * APAD + bsel * 4) * 4);
    uint32_t vt_b = sb + (uint32_t)((128 * APAD + 64 * APAD + 128 * APAD) * 4)
                       + (uint32_t)((brow * APAD + bsel * 4) * 4);
    const uint32_t MT_STEP = 16 * APAD * 4;   // bytes per m-tile
    const uint32_t N_STEP  = 8 * APAD * 4;    // bytes per n-tile (B)

    float oacc[2][8][4];
#pragma unroll
    for (int mt = 0; mt < 2; mt++)
#pragma unroll
        for (int n = 0; n < 8; n++)
#pragma unroll
            for (int j = 0; j < 4; j++) oacc[mt][n][j] = 0.0f;
    float mrow[2][2] = {{-1e30f, -1e30f}, {-1e30f, -1e30f}};
    float lrow[2][2] = {{0.0f, 0.0f}, {0.0f, 0.0f}};

    for (int kv0 = 0; kv0 < Tn; kv0 += 64) {
        // ---- K fill (tf32) ----
#pragma unroll
        for (int it = 0; it < 8; it++) {
            int idx = tid + it * 128;
            int r = idx >> 4;
            int c4 = (idx & 15) * 4;
            float4 v = *(const float4*)(kb + (size_t)(kv0 + r) * QKVN + c4);
            v.x = f2tf_f(v.x); v.y = f2tf_f(v.y);
            v.z = f2tf_f(v.z); v.w = f2tf_f(v.w);
            *(float4*)&Ks[r * APAD + c4] = v;
        }
        // ---- V fill transposed: Vt[d][kv] ----
#pragma unroll
        for (int it = 0; it < 8; it++) {
            int idx = tid + it * 128;
            int r = idx & 63;                 // kv row
            int c4 = (idx >> 6) * 4;          // d base
            float4 v = *(const float4*)(vb + (size_t)(kv0 + r) * QKVN + c4);
            Vt[(c4 + 0) * APAD + r] = f2tf_f(v.x);
            Vt[(c4 + 1) * APAD + r] = f2tf_f(v.y);
            Vt[(c4 + 2) * APAD + r] = f2tf_f(v.z);
            Vt[(c4 + 3) * APAD + r] = f2tf_f(v.w);
        }
        if (tid < 64)
            Ms[tid] = mask[b * Tn + kv0 + tid] ? -1e30f : 0.0f;
        __syncthreads();

        // ---- S = Q K^T ----
        float sacc[2][8][4];
#pragma unroll
        for (int mt = 0; mt < 2; mt++)
#pragma unroll
            for (int n = 0; n < 8; n++)
#pragma unroll
                for (int j = 0; j < 4; j++) sacc[mt][n][j] = 0.0f;

#pragma unroll
        for (int k = 0; k < 8; k++) {
            uint32_t a0[4], a1[4];
            ldsm4(a0[0], a0[1], a0[2], a0[3], qs_a + k * 32);
            ldsm4(a1[0], a1[1], a1[2], a1[3], qs_a + MT_STEP + k * 32);
#pragma unroll
            for (int n = 0; n < 8; n++) {
                uint32_t b0, b1;
                ldsm2(b0, b1, ks_b + n * N_STEP + k * 32);
                mma_tf32(sacc[0][n], a0[0], a0[1], a0[2], a0[3], b0, b1);
                mma_tf32(sacc[1][n], a1[0], a1[1], a1[2], a1[3], b0, b1);
            }
        }

        // ---- mask + online softmax ----
#pragma unroll
        for (int mt = 0; mt < 2; mt++) {
            float mx0 = -1e30f, mx1 = -1e30f;
#pragma unroll
            for (int n = 0; n < 8; n++) {
                int c = n * 8 + cq * 2;
                float ma = Ms[c], mb2 = Ms[c + 1];
                sacc[mt][n][0] += ma; sacc[mt][n][1] += mb2;
                sacc[mt][n][2] += ma; sacc[mt][n][3] += mb2;
                mx0 = fmaxf(mx0, fmaxf(sacc[mt][n][0], sacc[mt][n][1]));
                mx1 = fmaxf(mx1, fmaxf(sacc[mt][n][2], sacc[mt][n][3]));
            }
            mx0 = fmaxf(mx0, __shfl_xor_sync(0xffffffffu, mx0, 1));
            mx0 = fmaxf(mx0, __shfl_xor_sync(0xffffffffu, mx0, 2));
            mx1 = fmaxf(mx1, __shfl_xor_sync(0xffffffffu, mx1, 1));
            mx1 = fmaxf(mx1, __shfl_xor_sync(0xffffffffu, mx1, 2));

            float nm0 = fmaxf(mrow[mt][0], mx0);
            float nm1 = fmaxf(mrow[mt][1], mx1);
            float al0 = __expf(mrow[mt][0] - nm0);
            float al1 = __expf(mrow[mt][1] - nm1);
            float rs0 = 0.0f, rs1 = 0.0f;
#pragma unroll
            for (int n = 0; n < 8; n++) {
                sacc[mt][n][0] = __expf(sacc[mt][n][0] - nm0);
                sacc[mt][n][1] = __expf(sacc[mt][n][1] - nm0);
                sacc[mt][n][2] = __expf(sacc[mt][n][2] - nm1);
                sacc[mt][n][3] = __expf(sacc[mt][n][3] - nm1);
                rs0 += sacc[mt][n][0] + sacc[mt][n][1];
                rs1 += sacc[mt][n][2] + sacc[mt][n][3];
            }
            rs0 += __shfl_xor_sync(0xffffffffu, rs0, 1);
            rs0 += __shfl_xor_sync(0xffffffffu, rs0, 2);
            rs1 += __shfl_xor_sync(0xffffffffu, rs1, 1);
            rs1 += __shfl_xor_sync(0xffffffffu, rs1, 2);

            lrow[mt][0] = lrow[mt][0] * al0 + rs0;  mrow[mt][0] = nm0;
            lrow[mt][1] = lrow[mt][1] * al1 + rs1;  mrow[mt][1] = nm1;
#pragma unroll
            for (int n = 0; n < 8; n++) {
                oacc[mt][n][0] *= al0; oacc[mt][n][1] *= al0;
                oacc[mt][n][2] *= al1; oacc[mt][n][3] *= al1;
            }
        }

        // ---- store P (tf32; warp-private rows) ----
#pragma unroll
        for (int mt = 0; mt < 2; mt++) {
            int pr0 = (wrow + mt * 16 + r0) * APAD;
            int pr1 = pr0 + 8 * APAD;
#pragma unroll
            for (int n = 0; n < 8; n++) {
                int c = n * 8 + cq * 2;
                *(float2*)&Ps[pr0 + c] =
                    make_float2(f2tf_f(sacc[mt][n][0]), f2tf_f(sacc[mt][n][1]));
                *(float2*)&Ps[pr1 + c] =
                    make_float2(f2tf_f(sacc[mt][n][2]), f2tf_f(sacc[mt][n][3]));
            }
        }
        __syncwarp();

        // ---- O += P V ----
#pragma unroll
        for (int k = 0; k < 8; k++) {
            uint32_t p0[4], p1[4];
            ldsm4(p0[0], p0[1], p0[2], p0[3], ps_a + k * 32);
            ldsm4(p1[0], p1[1], p1[2], p1[3], ps_a + MT_STEP + k * 32);
#pragma unroll
            for (int n = 0; n < 8; n++) {
                uint32_t b0, b1;
                ldsm2(b0, b1, vt_b + n * N_STEP + k * 32);
                mma_tf32(oacc[0][n], p0[0], p0[1], p0[2], p0[3], b0, b1);
                mma_tf32(oacc[1][n], p1[0], p1[1], p1[2], p1[3], b0, b1);
            }
        }
        __syncthreads();
    }

    // ---- epilogue ----
#pragma unroll
    for (int mt = 0; mt < 2; mt++) {
        float inv0 = 1.0f / lrow[mt][0];
        float inv1 = 1.0f / lrow[mt][1];
        int row = q0 + wrow + mt * 16 + r0;
#pragma unroll
        for (int n = 0; n < 8; n++) {
            int col = h * HDn + n * 8 + cq * 2;
            float* p0 = &ctx[((size_t)b * Tn + row) * En + col];
            *(float2*)p0 = make_float2(oacc[mt][n][0] * inv0,
                                       oacc[mt][n][1] * inv0);
            float* p1 = &ctx[((size_t)b * Tn + row + 8) * En + col];
            *(float2*)p1 = make_float2(oacc[mt][n][2] * inv1,
                                       oacc[mt][n][3] * inv1);
        }
    }
}

// ---------------------------------------------------------------------------
extern "C" void kernel_launch(void* const* d_in, const int* in_sizes, int n_in,
                              void* d_out, int out_size) {
    const float*         x      = (const float*)d_in[0];
    const unsigned char* mask   = (const unsigned char*)d_in[1];
    const float*         qkv_w  = (const float*)d_in[2];
    const float*         qkv_b  = (const float*)d_in[3];
    const float*         proj_w = (const float*)d_in[4];
    const float*         proj_b = (const float*)d_in[5];
    float*               out    = (float*)d_out;

    float *qkv_s, *ctx_s;
    __nv_bfloat16 *xs, *ws, *cs, *pws;
    cudaGetSymbolAddress((void**)&qkv_s, g_qkv);
    cudaGetSymbolAddress((void**)&ctx_s, g_ctx);
    cudaGetSymbolAddress((void**)&xs,  g_xs);
    cudaGetSymbolAddress((void**)&ws,  g_ws);
    cudaGetSymbolAddress((void**)&cs,  g_cs);
    cudaGetSymbolAddress((void**)&pws, g_pws);

    cudaFuncSetAttribute(gemm_hmma,
                         cudaFuncAttributeMaxDynamicSharedMemorySize, GEMM_SMEM);
    cudaFuncSetAttribute(attn_tc,
                         cudaFuncAttributeMaxDynamicSharedMemorySize, ATTN3_SMEM);

    // 1) split x and qkv_w into bf16x3
    split3_kernel<<<(size_t)Mn * En / 4 / 256, 256>>>(x, xs, 1);
    split3_kernel<<<(size_t)QKVN * En / 4 / 256, 256>>>(qkv_w, ws, 2);

    // 2) QKV GEMM
    {
        dim3 grid(QKVN / 128, Mn / 128);
        gemm_hmma<<<grid, 256, GEMM_SMEM>>>(xs, ws, qkv_b, qkv_s, QKVN);
    }

    // 3) attention (tf32 tensor cores, ldmatrix, 128 q-rows/block)
    {
        dim3 grid(Tn / 128, Bn * Hn);
        attn_tc<<<grid, 128, ATTN3_SMEM>>>(qkv_s, mask, ctx_s);
    }

    // 4) split ctx and proj_w
    split3_kernel<<<(size_t)Mn * En / 4 / 256, 256>>>(ctx_s, cs, 1);
    split3_kernel<<<(size_t)En * En / 4 / 256, 256>>>(proj_w, pws, 2);

    // 5) proj GEMM
    {
        dim3 grid(En / 128, Mn / 128);
        gemm_hmma<<<grid, 256, GEMM_SMEM>>>(cs, pws, proj_b, out, En);
    }
}